// round 1
// baseline (speedup 1.0000x reference)
#include <cuda_runtime.h>
#include <cuda_bf16.h>
#include <cstdint>

#define BATCH 8
#define NANCH 25500
#define NCLS 80
#define PREDC 85
#define MAXDET 300
#define NBINS 1024
#define CANDMAX 4096
#define TOTDET (BATCH*MAXDET)   // 2400
#define FDIM 1920
#define HDIM 256
#define OUTC 260

// ---------------- scratch (static device globals; no allocation) ----------------
__device__ float g_conf[BATCH*NANCH];
__device__ int   g_cls [BATCH*NANCH];
__device__ int   g_hist[BATCH*NBINS];
__device__ int   g_thrbin[BATCH];
__device__ int   g_candcount[BATCH];
__device__ float g_candconf[BATCH*CANDMAX];
__device__ int   g_candidx [BATCH*CANDMAX];
__device__ float g_topv[TOTDET];
__device__ int   g_topi[TOTDET];
__device__ float g_boxes[TOTDET*4];
__device__ float g_keep [TOTDET];
__device__ float g_t1[BATCH*6400*128];
__device__ float g_t2[BATCH*1600*256];
__device__ float g_t3[BATCH*400*512];
__device__ float g_t4[BATCH*100*1024];
__device__ float g_F [TOTDET*FDIM];
__device__ float g_H1[TOTDET*HDIM];

// ---------------- K0: zero counters ----------------
__global__ void zero_kernel() {
    int i = blockIdx.x * 256 + threadIdx.x;
    if (i < BATCH*NBINS) g_hist[i] = 0;
    if (i < BATCH)       g_candcount[i] = 0;
}

// ---------------- K1: conf/cls + histogram ----------------
__global__ void __launch_bounds__(128) score_kernel(const float* __restrict__ preds) {
    __shared__ float s[128*PREDC];
    __shared__ int shist[NBINS];
    int b  = blockIdx.y;
    int n0 = blockIdx.x * 128;
    int cnt = NANCH - n0; if (cnt > 128) cnt = 128;
    for (int i = threadIdx.x; i < NBINS; i += 128) shist[i] = 0;
    const float* src = preds + ((size_t)b*NANCH + n0) * PREDC;
    int tot = cnt * PREDC;
    for (int i = threadIdx.x; i < tot; i += 128) s[i] = src[i];
    __syncthreads();
    int t = threadIdx.x;
    if (t < cnt) {
        const float* a = s + t*PREDC;
        float obj = a[4];
        float best = a[5]*obj; int bc = 0;
        #pragma unroll 8
        for (int c = 1; c < NCLS; c++) {
            float v = a[5+c]*obj;
            if (v > best) { best = v; bc = c; }
        }
        float conf = best > 0.1f ? best : 0.f;
        g_conf[(size_t)b*NANCH + n0 + t] = conf;
        g_cls [(size_t)b*NANCH + n0 + t] = bc;
        if (conf > 0.1f) {
            int bin = (int)((conf - 0.1f) * (1024.f/0.9f));
            bin = min(max(bin, 0), NBINS-1);
            atomicAdd(&shist[bin], 1);
        }
    }
    __syncthreads();
    for (int i = threadIdx.x; i < NBINS; i += 128) {
        int v = shist[i];
        if (v) atomicAdd(&g_hist[b*NBINS + i], v);
    }
}

// ---------------- K2: find threshold bin (suffix scan) ----------------
__global__ void __launch_bounds__(NBINS) thresh_kernel() {
    __shared__ int s[NBINS];
    int b = blockIdx.x, t = threadIdx.x;
    s[t] = g_hist[b*NBINS + t];
    __syncthreads();
    for (int off = 1; off < NBINS; off <<= 1) {
        int v = (t + off < NBINS) ? s[t + off] : 0;
        __syncthreads();
        s[t] += v;
        __syncthreads();
    }
    if (s[t] >= MAXDET && (t == NBINS-1 || s[t+1] < MAXDET)) g_thrbin[b] = t;
    if (t == 0 && s[0] < MAXDET) g_thrbin[b] = 0;
}

// ---------------- K3: compaction ----------------
__global__ void compact_kernel() {
    int b = blockIdx.y;
    int i = blockIdx.x * 256 + threadIdx.x;
    if (i >= NANCH) return;
    float conf = g_conf[(size_t)b*NANCH + i];
    if (conf > 0.1f) {
        int bin = (int)((conf - 0.1f) * (1024.f/0.9f));
        bin = min(max(bin, 0), NBINS-1);
        if (bin >= g_thrbin[b]) {
            int pos = atomicAdd(&g_candcount[b], 1);
            if (pos < CANDMAX) {
                g_candconf[b*CANDMAX + pos] = conf;
                g_candidx [b*CANDMAX + pos] = i;
            }
        }
    }
}

// ---------------- K4: exact stable rank -> top-300 ----------------
__global__ void __launch_bounds__(1024) rank_kernel() {
    __shared__ float cc[CANDMAX];
    __shared__ int   ci[CANDMAX];
    int b = blockIdx.x, t = threadIdx.x;
    int M = g_candcount[b]; if (M > CANDMAX) M = CANDMAX;
    for (int i = t; i < M; i += 1024) {
        cc[i] = g_candconf[b*CANDMAX + i];
        ci[i] = g_candidx [b*CANDMAX + i];
    }
    if (t < MAXDET) { g_topv[b*MAXDET + t] = 0.f; g_topi[b*MAXDET + t] = 0; }
    __syncthreads();
    for (int i = t; i < M; i += 1024) {
        float c = cc[i]; int id = ci[i];
        int r = 0;
        for (int j = 0; j < M; j++) {
            float cj = cc[j];
            r += (cj > c) || (cj == c && ci[j] < id);
        }
        if (r < MAXDET) { g_topv[b*MAXDET + r] = c; g_topi[b*MAXDET + r] = id; }
    }
}

// ---------------- K5: NMS (bitmask + serial greedy) ----------------
__global__ void __launch_bounds__(320) nms_kernel(const float* __restrict__ preds) {
    __shared__ float sx1[MAXDET], sy1[MAXDET], sx2[MAXDET], sy2[MAXDET], sar[MAXDET];
    __shared__ unsigned supm[MAXDET][10];
    __shared__ unsigned keepw[10];
    int b = blockIdx.x, t = threadIdx.x;
    bool act = t < MAXDET;
    float vx1=0.f, vy1=0.f, vx2=0.f, vy2=0.f;
    bool valid = false;
    if (act) {
        int idx = g_topi[b*MAXDET + t];
        float tv = g_topv[b*MAXDET + t];
        const float* p = preds + ((size_t)b*NANCH + idx) * PREDC;
        float xc = p[0], yc = p[1], w = p[2], h = p[3];
        float x1 = xc - w*0.5f, y1 = yc - h*0.5f;
        float x2 = xc + w*0.5f, y2 = yc + h*0.5f;
        float* gb = g_boxes + ((size_t)b*MAXDET + t)*4;
        gb[0]=x1; gb[1]=y1; gb[2]=x2; gb[3]=y2;
        float off = (float)g_cls[(size_t)b*NANCH + idx] * 4096.0f;
        vx1 = x1+off; vy1 = y1+off; vx2 = x2+off; vy2 = y2+off;
        sx1[t]=vx1; sy1[t]=vy1; sx2[t]=vx2; sy2[t]=vy2;
        sar[t] = (vx2-vx1)*(vy2-vy1);   // area on offset coords, matching ref fp exactly
        valid = tv > 0.1f;
    }
    int w10 = t >> 5, lane = t & 31;
    unsigned vb = __ballot_sync(0xffffffffu, valid);
    if (lane == 0) keepw[w10] = vb;
    __syncthreads();
    float myar = act ? sar[t] : 0.f;
    for (int i = 0; i < MAXDET; i++) {
        bool sup = false;
        if (act && t > i) {
            float lx  = fmaxf(sx1[i], vx1), lyv = fmaxf(sy1[i], vy1);
            float rx  = fminf(sx2[i], vx2), ry  = fminf(sy2[i], vy2);
            float iw  = fmaxf(rx - lx, 0.f), ih = fmaxf(ry - lyv, 0.f);
            float inter = iw * ih;
            float iou = inter / (sar[i] + myar - inter + 1e-7f);
            sup = iou > 0.6f;
        }
        unsigned m = __ballot_sync(0xffffffffu, sup);
        if (lane == 0) supm[i][w10] = m;
    }
    __syncthreads();
    if (t == 0) {
        for (int i = 0; i < MAXDET; i++) {
            if ((keepw[i>>5] >> (i&31)) & 1u) {
                #pragma unroll
                for (int w2 = 0; w2 < 10; w2++) keepw[w2] &= ~supm[i][w2];
            }
        }
    }
    __syncthreads();
    if (act) g_keep[b*MAXDET + t] = ((keepw[t>>5] >> (t&31)) & 1u) ? 1.f : 0.f;
}

// ---------------- K6: feature transpose (C,HW) -> (HW,C) ----------------
__global__ void transpose_kernel(const float* __restrict__ in, int level, int C, int HW) {
    __shared__ float tile[32][33];
    float* outbase = (level==0) ? g_t1 : (level==1) ? g_t2 : (level==2) ? g_t3 : g_t4;
    int b = blockIdx.z;
    const float* src = in + (size_t)b*C*HW;
    float* dst = outbase + (size_t)b*C*HW;
    int p0 = blockIdx.x*32, c0 = blockIdx.y*32;
    for (int i = threadIdx.y; i < 32; i += 8) {
        int c = c0 + i, p = p0 + threadIdx.x;
        if (c < C && p < HW) tile[i][threadIdx.x] = src[(size_t)c*HW + p];
    }
    __syncthreads();
    for (int i = threadIdx.y; i < 32; i += 8) {
        int p = p0 + i, c = c0 + threadIdx.x;
        if (c < C && p < HW) dst[(size_t)p*C + c] = tile[threadIdx.x][i];
    }
}

// ---------------- K7: ROI align 1x1 gather ----------------
template<int C, int H, int W>
__device__ __forceinline__ void roi_level(const float* __restrict__ T, float bx1, float by1,
                                          float bx2, float by2, float scale, float* __restrict__ out) {
    float x1 = bx1*scale, y1 = by1*scale, x2 = bx2*scale, y2 = by2*scale;
    float w = fmaxf(x2-x1, 1.f), h = fmaxf(y2-y1, 1.f);
    float xs[2] = { x1 + 0.5f*(w*0.5f), x1 + 1.5f*(w*0.5f) };
    float ys[2] = { y1 + 0.5f*(h*0.5f), y1 + 1.5f*(h*0.5f) };
    int pos[16]; float wt[16];
    int t = 0;
    #pragma unroll
    for (int py = 0; py < 2; py++) {
        #pragma unroll
        for (int px = 0; px < 2; px++) {
            float y = fminf(fmaxf(ys[py], 0.f), (float)(H-1));
            float x = fminf(fmaxf(xs[px], 0.f), (float)(W-1));
            float y0f = floorf(y), x0f = floorf(x);
            int y0 = (int)y0f, x0 = (int)x0f;
            int y1i = min(y0+1, H-1), x1i = min(x0+1, W-1);
            float ly = y - y0f, lx = x - x0f;
            pos[t] = (y0 *W + x0 )*C; wt[t] = (1.f-ly)*(1.f-lx)*0.25f; t++;
            pos[t] = (y0 *W + x1i)*C; wt[t] = (1.f-ly)*lx*0.25f;       t++;
            pos[t] = (y1i*W + x0 )*C; wt[t] = ly*(1.f-lx)*0.25f;       t++;
            pos[t] = (y1i*W + x1i)*C; wt[t] = ly*lx*0.25f;             t++;
        }
    }
    for (int c = threadIdx.x; c < C; c += 256) {
        float acc = 0.f;
        #pragma unroll
        for (int k = 0; k < 16; k++) acc += wt[k] * T[pos[k] + c];
        out[c] = acc;
    }
}

__global__ void __launch_bounds__(256) roi_kernel() {
    int det = blockIdx.x, b = blockIdx.y;
    int row = b*MAXDET + det;
    const float* gb = g_boxes + (size_t)row*4;
    float x1 = gb[0], y1 = gb[1], x2 = gb[2], y2 = gb[3];
    float* out = g_F + (size_t)row*FDIM;
    roi_level<128, 80, 80>(g_t1 + (size_t)b*6400*128, x1,y1,x2,y2, 0.125f,    out + 0);
    roi_level<256, 40, 40>(g_t2 + (size_t)b*1600*256, x1,y1,x2,y2, 0.0625f,   out + 128);
    roi_level<512, 20, 20>(g_t3 + (size_t)b*400*512,  x1,y1,x2,y2, 0.03125f,  out + 384);
    roi_level<1024,10, 10>(g_t4 + (size_t)b*100*1024, x1,y1,x2,y2, 0.015625f, out + 896);
}

// ---------------- K8/K9: GEMM (BM=16, BN=256, 150 blocks = 1/SM) ----------------
template<int K, bool LAYER2>
__global__ void __launch_bounds__(256) gemm_bm16(const float* __restrict__ Bw,
                                                 const float* __restrict__ bias,
                                                 float* __restrict__ outp) {
    __shared__ float As[16][17];
    __shared__ float Bs[16][256];
    const float* A = LAYER2 ? g_H1 : g_F;
    int m0 = blockIdx.x * 16;
    int tid = threadIdx.x;
    int ty = tid >> 6;    // 0..3 : rows ty*4..
    int tx = tid & 63;    // cols tx*4..
    float acc[4][4] = {};
    for (int k0 = 0; k0 < K; k0 += 16) {
        if (tid < 64) {
            int r = tid >> 2, f = tid & 3;
            float4 av = *(const float4*)(A + (size_t)(m0 + r)*K + k0 + f*4);
            As[f*4+0][r] = av.x; As[f*4+1][r] = av.y;
            As[f*4+2][r] = av.z; As[f*4+3][r] = av.w;
        }
        {
            int r = tid >> 6, f = tid & 63;
            #pragma unroll
            for (int i = 0; i < 4; i++) {
                int rowk = r + i*4;
                *(float4*)&Bs[rowk][f*4] = *(const float4*)(Bw + (size_t)(k0 + rowk)*256 + f*4);
            }
        }
        __syncthreads();
        #pragma unroll
        for (int k = 0; k < 16; k++) {
            float a0 = As[k][ty*4+0], a1 = As[k][ty*4+1];
            float a2 = As[k][ty*4+2], a3 = As[k][ty*4+3];
            float4 bq = *(float4*)&Bs[k][tx*4];
            acc[0][0] += a0*bq.x; acc[0][1] += a0*bq.y; acc[0][2] += a0*bq.z; acc[0][3] += a0*bq.w;
            acc[1][0] += a1*bq.x; acc[1][1] += a1*bq.y; acc[1][2] += a1*bq.z; acc[1][3] += a1*bq.w;
            acc[2][0] += a2*bq.x; acc[2][1] += a2*bq.y; acc[2][2] += a2*bq.z; acc[2][3] += a2*bq.w;
            acc[3][0] += a3*bq.x; acc[3][1] += a3*bq.y; acc[3][2] += a3*bq.z; acc[3][3] += a3*bq.w;
        }
        __syncthreads();
    }
    #pragma unroll
    for (int i = 0; i < 4; i++) {
        int m = m0 + ty*4 + i;
        float kf = LAYER2 ? g_keep[m] : 1.f;
        #pragma unroll
        for (int j = 0; j < 4; j++) {
            int n = tx*4 + j;
            float v = acc[i][j] + bias[n];
            v = v > 0.f ? v : 0.01f*v;
            if (LAYER2) outp[(size_t)m*OUTC + 4 + n] = v * kf;
            else        g_H1[(size_t)m*HDIM + n]     = v;
        }
    }
}

// ---------------- K10: box rescale ----------------
__global__ void bb_kernel(const float* __restrict__ orig_hw, float* __restrict__ out) {
    int m = blockIdx.x * 256 + threadIdx.x;
    if (m >= TOTDET) return;
    int b = m / MAXDET;
    const float* gb = g_boxes + (size_t)m*4;
    float oh = orig_hw[b*2 + 0], ow = orig_hw[b*2 + 1];
    float gain = fminf(640.f/oh, 640.f/ow);
    float padx = (640.f - ow*gain) * 0.5f;
    float pady = (640.f - oh*gain) * 0.5f;
    float kf = g_keep[m];
    float x1 = fminf(fmaxf((gb[0]-padx)/gain, 0.f), ow);
    float y1 = fminf(fmaxf((gb[1]-pady)/gain, 0.f), oh);
    float x2 = fminf(fmaxf((gb[2]-padx)/gain, 0.f), ow);
    float y2 = fminf(fmaxf((gb[3]-pady)/gain, 0.f), oh);
    float* o = out + (size_t)m*OUTC;
    o[0] = x1/ow*kf; o[1] = y1/oh*kf; o[2] = x2/ow*kf; o[3] = y2/oh*kf;
}

// ---------------- launch ----------------
extern "C" void kernel_launch(void* const* d_in, const int* in_sizes, int n_in,
                              void* d_out, int out_size) {
    const float* preds   = (const float*)d_in[0];
    const float* feat1   = (const float*)d_in[1];
    const float* feat2   = (const float*)d_in[2];
    const float* feat3   = (const float*)d_in[3];
    const float* feat4   = (const float*)d_in[4];
    const float* orig_hw = (const float*)d_in[5];
    const float* W1      = (const float*)d_in[6];
    const float* b1      = (const float*)d_in[7];
    const float* W2      = (const float*)d_in[8];
    const float* b2      = (const float*)d_in[9];
    float* out = (float*)d_out;
    (void)in_sizes; (void)n_in; (void)out_size;

    zero_kernel<<<32, 256>>>();
    score_kernel<<<dim3(200, BATCH), 128>>>(preds);
    thresh_kernel<<<BATCH, NBINS>>>();
    compact_kernel<<<dim3(100, BATCH), 256>>>();
    rank_kernel<<<BATCH, 1024>>>();
    nms_kernel<<<BATCH, 320>>>(preds);

    dim3 tb(32, 8);
    transpose_kernel<<<dim3(200,  4, BATCH), tb>>>(feat1, 0, 128, 6400);
    transpose_kernel<<<dim3( 50,  8, BATCH), tb>>>(feat2, 1, 256, 1600);
    transpose_kernel<<<dim3( 13, 16, BATCH), tb>>>(feat3, 2, 512,  400);
    transpose_kernel<<<dim3(  4, 32, BATCH), tb>>>(feat4, 3, 1024, 100);

    roi_kernel<<<dim3(MAXDET, BATCH), 256>>>();

    gemm_bm16<FDIM, false><<<TOTDET/16, 256>>>(W1, b1, nullptr);
    gemm_bm16<HDIM, true ><<<TOTDET/16, 256>>>(W2, b2, out);

    bb_kernel<<<(TOTDET + 255)/256, 256>>>(orig_hw, out);
}

// round 3
// speedup vs baseline: 1.9500x; 1.9500x over previous
#include <cuda_runtime.h>
#include <cstdint>

#define BATCH 8
#define NANCH 25500
#define NCLS 80
#define PREDC 85
#define MAXDET 300
#define NBINS 1024
#define CMAX 1024
#define TOTDET (BATCH*MAXDET)   // 2400
#define FDIM 1920
#define HDIM 256
#define OUTC 260
#define NSLAB 4
#define KSLAB (FDIM/NSLAB)      // 480
#define NKT1 (KSLAB/16)         // 30
#define NKT2 (HDIM/16)          // 16

typedef unsigned long long ull;

// ---------------- scratch (static device globals; no allocation) ----------------
__device__ __align__(16) float g_conf[BATCH*NANCH];
__device__ int   g_cls [BATCH*NANCH];
__device__ int   g_hist[BATCH*NBINS];
__device__ __align__(16) float g_boxes[TOTDET*4];
__device__ float g_keep [TOTDET];
__device__ __align__(16) float g_t1[BATCH*6400*128];
__device__ __align__(16) float g_t2[BATCH*1600*256];
__device__ __align__(16) float g_t3[BATCH*400*512];
__device__ __align__(16) float g_t4[BATCH*100*1024];
__device__ __align__(16) float g_F [TOTDET*FDIM];
__device__ __align__(16) float g_part[NSLAB*TOTDET*HDIM];

// ---------------- asm helpers ----------------
__device__ __forceinline__ void cp16(void* s, const void* g) {
    unsigned ss = (unsigned)__cvta_generic_to_shared(s);
    asm volatile("cp.async.cg.shared.global [%0], [%1], 16;" :: "r"(ss), "l"(g));
}
#define CPCOMMIT asm volatile("cp.async.commit_group;" ::: "memory")
#define FFMA2(d,a,b) asm volatile("fma.rn.f32x2 %0, %1, %2, %0;" : "+l"(d) : "l"(a), "l"(b))
#define PACKDUP(d,x) asm volatile("mov.b64 %0, {%1, %1};" : "=l"(d) : "f"(x))
#define UNPACK2(lo,hi,v) asm volatile("mov.b64 {%0, %1}, %2;" : "=f"(lo), "=f"(hi) : "l"(v))

// ---------------- K0: zero hist ----------------
__global__ void zero_kernel() {
    g_hist[blockIdx.x*1024 + threadIdx.x] = 0;
}

// ---------------- K1: conf/cls + histogram ----------------
__global__ void __launch_bounds__(128) score_kernel(const float* __restrict__ preds) {
    __shared__ __align__(16) float s[128*PREDC];
    __shared__ int shist[NBINS];
    int b  = blockIdx.y;
    int n0 = blockIdx.x * 128;
    int cnt = NANCH - n0; if (cnt > 128) cnt = 128;
    for (int i = threadIdx.x; i < NBINS; i += 128) shist[i] = 0;
    const float4* src = (const float4*)(preds + ((size_t)b*NANCH + n0) * PREDC);
    float4* s4 = (float4*)s;
    int tot4 = cnt * PREDC / 4;
    for (int i = threadIdx.x; i < tot4; i += 128) s4[i] = src[i];
    __syncthreads();
    int t = threadIdx.x;
    if (t < cnt) {
        const float* a = s + t*PREDC;
        float obj = a[4];
        float best = a[5]*obj; int bc = 0;
        #pragma unroll 8
        for (int c = 1; c < NCLS; c++) {
            float v = a[5+c]*obj;
            if (v > best) { best = v; bc = c; }
        }
        float conf = best > 0.1f ? best : 0.f;
        g_conf[(size_t)b*NANCH + n0 + t] = conf;
        g_cls [(size_t)b*NANCH + n0 + t] = bc;
        if (conf > 0.1f) {
            int bin = (int)((conf - 0.1f) * (1024.f/0.9f));
            bin = min(max(bin, 0), NBINS-1);
            atomicAdd(&shist[bin], 1);
        }
    }
    __syncthreads();
    for (int i = threadIdx.x; i < NBINS; i += 128) {
        int v = shist[i];
        if (v) atomicAdd(&g_hist[b*NBINS + i], v);
    }
}

// ---------------- K2: fused threshold + compact + rank + NMS ----------------
__global__ void __launch_bounds__(1024) select_kernel(const float* __restrict__ preds) {
    __shared__ int s[NBINS];
    __shared__ int sthr, scnt;
    __shared__ float cc[CMAX];
    __shared__ int   ci[CMAX];
    __shared__ float tv[MAXDET];
    __shared__ int   tti[MAXDET];
    __shared__ float sx1[MAXDET], sy1[MAXDET], sx2[MAXDET], sy2[MAXDET], sar[MAXDET];
    __shared__ int   scls[MAXDET];
    __shared__ unsigned supm[MAXDET][10];
    __shared__ unsigned keepw[10];
    int b = blockIdx.x, t = threadIdx.x;

    // --- phase 1: suffix scan of histogram -> threshold bin ---
    s[t] = g_hist[b*NBINS + t];
    __syncthreads();
    for (int off = 1; off < NBINS; off <<= 1) {
        int v = (t + off < NBINS) ? s[t + off] : 0;
        __syncthreads();
        s[t] += v;
        __syncthreads();
    }
    if (s[t] >= MAXDET && (t == NBINS-1 || s[t+1] < MAXDET)) sthr = t;
    if (t == 0) { if (s[0] < MAXDET) sthr = 0; scnt = 0; }
    __syncthreads();
    int thr = sthr;

    // --- phase 2: compact candidates into shared ---
    for (int i = t; i < NANCH; i += 1024) {
        float conf = g_conf[(size_t)b*NANCH + i];
        if (conf > 0.1f) {
            int bin = (int)((conf - 0.1f) * (1024.f/0.9f));
            bin = min(max(bin, 0), NBINS-1);
            if (bin >= thr) {
                int p = atomicAdd(&scnt, 1);
                if (p < CMAX) { cc[p] = conf; ci[p] = i; }
            }
        }
    }
    __syncthreads();
    int M = min(scnt, CMAX);

    // --- phase 3: exact stable rank -> top-300 ---
    if (t < MAXDET) { tv[t] = 0.f; tti[t] = 0; }
    __syncthreads();
    for (int i = t; i < M; i += 1024) {
        float c = cc[i]; int id = ci[i];
        int r = 0;
        for (int j = 0; j < M; j++) {
            float cj = cc[j];
            r += (cj > c) || (cj == c && ci[j] < id);
        }
        if (r < MAXDET) { tv[r] = c; tti[r] = id; }
    }
    __syncthreads();

    // --- phase 4: boxes + validity ---
    bool act = t < MAXDET;
    bool valid = false;
    if (act) {
        int idx = tti[t];
        float conf = tv[t];
        const float* p = preds + ((size_t)b*NANCH + idx) * PREDC;
        float xc = p[0], yc = p[1], w = p[2], h = p[3];
        float x1 = xc - w*0.5f, y1 = yc - h*0.5f;
        float x2 = xc + w*0.5f, y2 = yc + h*0.5f;
        float* gb = g_boxes + ((size_t)b*MAXDET + t)*4;
        gb[0]=x1; gb[1]=y1; gb[2]=x2; gb[3]=y2;
        int cls = g_cls[(size_t)b*NANCH + idx];
        float off = (float)cls * 4096.0f;
        float vx1 = x1+off, vy1 = y1+off, vx2 = x2+off, vy2 = y2+off;
        sx1[t]=vx1; sy1[t]=vy1; sx2[t]=vx2; sy2[t]=vy2;
        sar[t] = (vx2-vx1)*(vy2-vy1);
        scls[t] = cls;
        valid = conf > 0.1f;
    }
    if (t < 320) {
        unsigned vb = __ballot_sync(0xffffffffu, valid);
        if ((t & 31) == 0) keepw[t >> 5] = vb;
    }
    __syncthreads();

    // --- phase 5: suppression matrix, 32 warps over (i, word) jobs ---
    {
        int warp = t >> 5, lane = t & 31;
        for (int job = warp; job < MAXDET*10; job += 32) {
            int i = job / 10, word = job - i*10;
            int jb = word*32 + lane;
            int ic = scls[i];
            bool lact = (jb < MAXDET) && (jb > i);
            bool cm = lact && (scls[jb] == ic);
            unsigned anym = __ballot_sync(0xffffffffu, cm);
            bool sup = false;
            if (anym) {
                float ix1 = sx1[i], iy1 = sy1[i], ix2 = sx2[i], iy2 = sy2[i], iar = sar[i];
                if (cm) {
                    float lx = fmaxf(ix1, sx1[jb]), lyv = fmaxf(iy1, sy1[jb]);
                    float rx = fminf(ix2, sx2[jb]), ry  = fminf(iy2, sy2[jb]);
                    float iw = fmaxf(rx - lx, 0.f), ih = fmaxf(ry - lyv, 0.f);
                    float inter = iw * ih;
                    float iou = inter / (iar + sar[jb] - inter + 1e-7f);
                    sup = iou > 0.6f;
                }
            }
            unsigned m = __ballot_sync(0xffffffffu, sup);
            if (lane == 0) supm[i][word] = m;
        }
    }
    __syncthreads();

    // --- phase 6: greedy sweep (register keep words, ffs skip) ---
    if (t == 0) {
        unsigned kw[10];
        #pragma unroll
        for (int w = 0; w < 10; w++) kw[w] = keepw[w];
        #pragma unroll
        for (int w = 0; w < 10; w++) {
            unsigned bits = kw[w];
            while (bits) {
                int bit = __ffs(bits) - 1;
                bits &= bits - 1;
                int i = w*32 + bit;
                #pragma unroll
                for (int w2 = 0; w2 < 10; w2++) kw[w2] &= ~supm[i][w2];
                bits &= kw[w];
            }
        }
        #pragma unroll
        for (int w = 0; w < 10; w++) keepw[w] = kw[w];
    }
    __syncthreads();
    if (act) g_keep[b*MAXDET + t] = ((keepw[t>>5] >> (t&31)) & 1u) ? 1.f : 0.f;
}

// ---------------- K3: merged feature transpose (C,HW) -> (HW,C) ----------------
__global__ void __launch_bounds__(256) transpose_kernel(const float* __restrict__ f1,
        const float* __restrict__ f2, const float* __restrict__ f3, const float* __restrict__ f4) {
    __shared__ float tile[32][33];
    int tl = blockIdx.x, b = blockIdx.y;
    const float* src; float* dst; int C, HW, tp;
    if (tl < 800)       {            src = f1; dst = g_t1; C = 128;  HW = 6400; tp = 200; }
    else if (tl < 1200) { tl -= 800;  src = f2; dst = g_t2; C = 256;  HW = 1600; tp = 50; }
    else if (tl < 1408) { tl -= 1200; src = f3; dst = g_t3; C = 512;  HW = 400;  tp = 13; }
    else                { tl -= 1408; src = f4; dst = g_t4; C = 1024; HW = 100;  tp = 4; }
    src += (size_t)b*C*HW; dst += (size_t)b*C*HW;
    int p0 = (tl % tp) * 32, c0 = (tl / tp) * 32;
    for (int i = threadIdx.y; i < 32; i += 8) {
        int c = c0 + i, p = p0 + threadIdx.x;
        if (c < C && p < HW) tile[i][threadIdx.x] = src[(size_t)c*HW + p];
    }
    __syncthreads();
    for (int i = threadIdx.y; i < 32; i += 8) {
        int p = p0 + i, c = c0 + threadIdx.x;
        if (c < C && p < HW) dst[(size_t)p*C + c] = tile[threadIdx.x][i];
    }
}

// ---------------- K4: ROI align 1x1 (480 threads = one float4 chunk each) ----------------
__global__ void __launch_bounds__(480) roi_kernel() {
    int det = blockIdx.x, b = blockIdx.y;
    int row = b*MAXDET + det;
    const float* gb = g_boxes + (size_t)row*4;
    float bx1 = gb[0], by1 = gb[1], bx2 = gb[2], by2 = gb[3];
    int q = threadIdx.x;
    const float* T; int C, H, W; float scale; int c0;
    if (q < 32)       { T = g_t1 + (size_t)b*6400*128; C = 128;  H = 80; W = 80; scale = 0.125f;    c0 = q*4; }
    else if (q < 96)  { T = g_t2 + (size_t)b*1600*256; C = 256;  H = 40; W = 40; scale = 0.0625f;   c0 = (q-32)*4; }
    else if (q < 224) { T = g_t3 + (size_t)b*400*512;  C = 512;  H = 20; W = 20; scale = 0.03125f;  c0 = (q-96)*4; }
    else              { T = g_t4 + (size_t)b*100*1024; C = 1024; H = 10; W = 10; scale = 0.015625f; c0 = (q-224)*4; }

    float x1 = bx1*scale, y1 = by1*scale, x2 = bx2*scale, y2 = by2*scale;
    float w = fmaxf(x2-x1, 1.f), h = fmaxf(y2-y1, 1.f);
    float xs[2] = { x1 + 0.5f*(w*0.5f), x1 + 1.5f*(w*0.5f) };
    float ys[2] = { y1 + 0.5f*(h*0.5f), y1 + 1.5f*(h*0.5f) };
    int pos[16]; float wt[16];
    int k = 0;
    #pragma unroll
    for (int py = 0; py < 2; py++) {
        #pragma unroll
        for (int px = 0; px < 2; px++) {
            float y = fminf(fmaxf(ys[py], 0.f), (float)(H-1));
            float x = fminf(fmaxf(xs[px], 0.f), (float)(W-1));
            float y0f = floorf(y), x0f = floorf(x);
            int y0 = (int)y0f, x0 = (int)x0f;
            int y1i = min(y0+1, H-1), x1i = min(x0+1, W-1);
            float ly = y - y0f, lx = x - x0f;
            pos[k] = (y0 *W + x0 )*C; wt[k] = (1.f-ly)*(1.f-lx)*0.25f; k++;
            pos[k] = (y0 *W + x1i)*C; wt[k] = (1.f-ly)*lx*0.25f;       k++;
            pos[k] = (y1i*W + x0 )*C; wt[k] = ly*(1.f-lx)*0.25f;       k++;
            pos[k] = (y1i*W + x1i)*C; wt[k] = ly*lx*0.25f;             k++;
        }
    }
    float4 acc = make_float4(0.f, 0.f, 0.f, 0.f);
    #pragma unroll
    for (int i = 0; i < 16; i++) {
        float4 v = *(const float4*)(T + pos[i] + c0);
        float wv = wt[i];
        acc.x += wv*v.x; acc.y += wv*v.y; acc.z += wv*v.z; acc.w += wv*v.w;
    }
    *(float4*)(g_F + (size_t)row*FDIM + q*4) = acc;
}

// ---------------- K5: GEMM1 split-K (600 blocks, 64 thr, FFMA2, cp.async x2) ----------------
__global__ void __launch_bounds__(64) gemm1_kernel(const float* __restrict__ W1) {
    __shared__ __align__(16) float As[2][16][16];   // [stage][k][m]
    __shared__ __align__(16) float Bs[2][16][256];  // [stage][k][n]
    int m0 = blockIdx.x * 16;
    int slab = blockIdx.y;
    int kb = slab * KSLAB;
    int tid = threadIdx.x;
    int ar = tid >> 2, af = tid & 3;
    const float* Aptr = g_F + (size_t)(m0 + ar)*FDIM + kb + af*4;

    // prologue: stage 0
    {
        const float* bsrc = W1 + (size_t)kb*256 + tid*4;
        #pragma unroll
        for (int i = 0; i < 16; i++) cp16(&Bs[0][i][tid*4], bsrc + (size_t)i*256);
        CPCOMMIT;
        float4 av = *(const float4*)(Aptr);
        As[0][af*4+0][ar] = av.x; As[0][af*4+1][ar] = av.y;
        As[0][af*4+2][ar] = av.z; As[0][af*4+3][ar] = av.w;
    }

    int rg = tid >> 5;   // 0..1 -> rows rg*8..rg*8+7
    int cg = tid & 31;   // cols cg*4..+3 and 128+cg*4..+3
    ull acc[4][8];
    #pragma unroll
    for (int p = 0; p < 4; p++)
        #pragma unroll
        for (int j = 0; j < 8; j++) acc[p][j] = 0ull;

    #pragma unroll 1
    for (int kt = 0; kt < NKT1; kt++) {
        int st = kt & 1;
        if (kt + 1 < NKT1) {
            const float* bsrc = W1 + (size_t)(kb + (kt+1)*16)*256 + tid*4;
            #pragma unroll
            for (int i = 0; i < 16; i++) cp16(&Bs[st^1][i][tid*4], bsrc + (size_t)i*256);
            CPCOMMIT;
            float4 av = *(const float4*)(Aptr + (kt+1)*16);
            As[st^1][af*4+0][ar] = av.x; As[st^1][af*4+1][ar] = av.y;
            As[st^1][af*4+2][ar] = av.z; As[st^1][af*4+3][ar] = av.w;
            asm volatile("cp.async.wait_group 1;" ::: "memory");
        } else {
            asm volatile("cp.async.wait_group 0;" ::: "memory");
        }
        __syncthreads();
        #pragma unroll
        for (int k = 0; k < 16; k++) {
            ull a[4];
            #pragma unroll
            for (int p = 0; p < 4; p++)
                a[p] = *(const ull*)&As[st][k][rg*8 + 2*p];
            float4 b0 = *(const float4*)&Bs[st][k][cg*4];
            float4 b1 = *(const float4*)&Bs[st][k][128 + cg*4];
            ull bd[8];
            PACKDUP(bd[0], b0.x); PACKDUP(bd[1], b0.y); PACKDUP(bd[2], b0.z); PACKDUP(bd[3], b0.w);
            PACKDUP(bd[4], b1.x); PACKDUP(bd[5], b1.y); PACKDUP(bd[6], b1.z); PACKDUP(bd[7], b1.w);
            #pragma unroll
            for (int p = 0; p < 4; p++)
                #pragma unroll
                for (int j = 0; j < 8; j++) FFMA2(acc[p][j], a[p], bd[j]);
        }
        __syncthreads();
    }

    float* dst = g_part + ((size_t)slab*TOTDET + m0)*HDIM;
    #pragma unroll
    for (int p = 0; p < 4; p++) {
        float lo[8], hi[8];
        #pragma unroll
        for (int j = 0; j < 8; j++) UNPACK2(lo[j], hi[j], acc[p][j]);
        int r0 = rg*8 + 2*p;
        *(float4*)(dst + (size_t)r0*HDIM + cg*4)           = make_float4(lo[0],lo[1],lo[2],lo[3]);
        *(float4*)(dst + (size_t)r0*HDIM + 128 + cg*4)     = make_float4(lo[4],lo[5],lo[6],lo[7]);
        *(float4*)(dst + (size_t)(r0+1)*HDIM + cg*4)       = make_float4(hi[0],hi[1],hi[2],hi[3]);
        *(float4*)(dst + (size_t)(r0+1)*HDIM + 128 + cg*4) = make_float4(hi[4],hi[5],hi[6],hi[7]);
    }
}

// ---------------- K6: GEMM2 + slab reduce + bias/leaky + keep + bb ----------------
__global__ void __launch_bounds__(256) gemm2_kernel(const float* __restrict__ W2,
        const float* __restrict__ b1, const float* __restrict__ b2,
        const float* __restrict__ orig_hw, float* __restrict__ out) {
    __shared__ __align__(16) float Ah[HDIM][16];     // [k][m], 16KB
    __shared__ __align__(16) float Bs[2][16][256];   // 32KB
    int m0 = blockIdx.x * 16;
    int tid = threadIdx.x;

    // A panel: reduce 4 slabs + b1 + leaky, store transposed
    #pragma unroll
    for (int q = 0; q < 4; q++) {
        int pos = q*256 + tid;
        int r = pos >> 6, f = pos & 63;
        const float* p0 = g_part + ((size_t)(m0 + r))*HDIM + f*4;
        float4 s0 = *(const float4*)p0;
        float4 s1 = *(const float4*)(p0 + (size_t)TOTDET*HDIM);
        float4 s2 = *(const float4*)(p0 + (size_t)2*TOTDET*HDIM);
        float4 s3 = *(const float4*)(p0 + (size_t)3*TOTDET*HDIM);
        float4 bv = *(const float4*)(b1 + f*4);
        float v0 = s0.x+s1.x+s2.x+s3.x+bv.x; v0 = v0 > 0.f ? v0 : 0.01f*v0;
        float v1 = s0.y+s1.y+s2.y+s3.y+bv.y; v1 = v1 > 0.f ? v1 : 0.01f*v1;
        float v2 = s0.z+s1.z+s2.z+s3.z+bv.z; v2 = v2 > 0.f ? v2 : 0.01f*v2;
        float v3 = s0.w+s1.w+s2.w+s3.w+bv.w; v3 = v3 > 0.f ? v3 : 0.01f*v3;
        Ah[f*4+0][r] = v0; Ah[f*4+1][r] = v1; Ah[f*4+2][r] = v2; Ah[f*4+3][r] = v3;
    }

    // prologue B stage 0
    {
        int br = tid >> 6, bf = tid & 63;
        #pragma unroll
        for (int i = 0; i < 4; i++)
            cp16(&Bs[0][br + i*4][bf*4], W2 + (size_t)(br + i*4)*256 + bf*4);
        CPCOMMIT;
    }
    __syncthreads();

    int ty = tid >> 6, tx = tid & 63;
    ull acc[2][4];
    #pragma unroll
    for (int h = 0; h < 2; h++)
        #pragma unroll
        for (int j = 0; j < 4; j++) acc[h][j] = 0ull;

    #pragma unroll 1
    for (int kt = 0; kt < NKT2; kt++) {
        int st = kt & 1;
        if (kt + 1 < NKT2) {
            int br = tid >> 6, bf = tid & 63;
            #pragma unroll
            for (int i = 0; i < 4; i++)
                cp16(&Bs[st^1][br + i*4][bf*4], W2 + (size_t)((kt+1)*16 + br + i*4)*256 + bf*4);
            CPCOMMIT;
            asm volatile("cp.async.wait_group 1;" ::: "memory");
        } else {
            asm volatile("cp.async.wait_group 0;" ::: "memory");
        }
        __syncthreads();
        #pragma unroll
        for (int k = 0; k < 16; k++) {
            int kk = kt*16 + k;
            ull a0 = *(const ull*)&Ah[kk][ty*4];
            ull a1 = *(const ull*)&Ah[kk][ty*4 + 2];
            float4 bq = *(const float4*)&Bs[st][k][tx*4];
            ull bd[4];
            PACKDUP(bd[0], bq.x); PACKDUP(bd[1], bq.y); PACKDUP(bd[2], bq.z); PACKDUP(bd[3], bq.w);
            #pragma unroll
            for (int j = 0; j < 4; j++) { FFMA2(acc[0][j], a0, bd[j]); FFMA2(acc[1][j], a1, bd[j]); }
        }
        __syncthreads();
    }

    // epilogue: b2 + leaky + keep, write h part
    float4 bv2 = *(const float4*)(b2 + tx*4);
    float bb2[4] = { bv2.x, bv2.y, bv2.z, bv2.w };
    #pragma unroll
    for (int h = 0; h < 2; h++) {
        float lo[4], hi[4];
        #pragma unroll
        for (int j = 0; j < 4; j++) UNPACK2(lo[j], hi[j], acc[h][j]);
        int mr = m0 + ty*4 + 2*h;
        float kf0 = g_keep[mr], kf1 = g_keep[mr+1];
        float o0[4], o1[4];
        #pragma unroll
        for (int j = 0; j < 4; j++) {
            float v = lo[j] + bb2[j]; v = v > 0.f ? v : 0.01f*v; o0[j] = v * kf0;
            float u = hi[j] + bb2[j]; u = u > 0.f ? u : 0.01f*u; o1[j] = u * kf1;
        }
        *(float4*)(out + (size_t)mr*OUTC + 4 + tx*4)     = make_float4(o0[0],o0[1],o0[2],o0[3]);
        *(float4*)(out + (size_t)(mr+1)*OUTC + 4 + tx*4) = make_float4(o1[0],o1[1],o1[2],o1[3]);
    }

    // bb rescale (cols 0..3)
    if (tid < 16) {
        int m = m0 + tid;
        int bidx = m / MAXDET;
        const float* gb = g_boxes + (size_t)m*4;
        float oh = orig_hw[bidx*2 + 0], ow = orig_hw[bidx*2 + 1];
        float gain = fminf(640.f/oh, 640.f/ow);
        float padx = (640.f - ow*gain) * 0.5f;
        float pady = (640.f - oh*gain) * 0.5f;
        float kf = g_keep[m];
        float x1 = fminf(fmaxf((gb[0]-padx)/gain, 0.f), ow);
        float y1 = fminf(fmaxf((gb[1]-pady)/gain, 0.f), oh);
        float x2 = fminf(fmaxf((gb[2]-padx)/gain, 0.f), ow);
        float y2 = fminf(fmaxf((gb[3]-pady)/gain, 0.f), oh);
        *(float4*)(out + (size_t)m*OUTC) = make_float4(x1/ow*kf, y1/oh*kf, x2/ow*kf, y2/oh*kf);
    }
}

// ---------------- launch ----------------
extern "C" void kernel_launch(void* const* d_in, const int* in_sizes, int n_in,
                              void* d_out, int out_size) {
    const float* preds   = (const float*)d_in[0];
    const float* feat1   = (const float*)d_in[1];
    const float* feat2   = (const float*)d_in[2];
    const float* feat3   = (const float*)d_in[3];
    const float* feat4   = (const float*)d_in[4];
    const float* orig_hw = (const float*)d_in[5];
    const float* W1      = (const float*)d_in[6];
    const float* b1      = (const float*)d_in[7];
    const float* W2      = (const float*)d_in[8];
    const float* b2      = (const float*)d_in[9];
    float* out = (float*)d_out;
    (void)in_sizes; (void)n_in; (void)out_size;

    zero_kernel<<<8, 1024>>>();
    score_kernel<<<dim3(200, BATCH), 128>>>(preds);
    select_kernel<<<BATCH, 1024>>>(preds);
    transpose_kernel<<<dim3(1536, BATCH), dim3(32, 8)>>>(feat1, feat2, feat3, feat4);
    roi_kernel<<<dim3(MAXDET, BATCH), 480>>>();
    gemm1_kernel<<<dim3(TOTDET/16, NSLAB), 64>>>(W1);
    gemm2_kernel<<<TOTDET/16, 256>>>(W2, b1, b2, orig_hw, out);
}

// round 5
// speedup vs baseline: 2.0465x; 1.0495x over previous
#include <cuda_runtime.h>
#include <cstdint>

#define BATCH 8
#define NANCH 25500
#define NCLS 80
#define PREDC 85
#define MAXDET 300
#define NBINS 1024
#define CMAX 1024
#define TOTDET (BATCH*MAXDET)   // 2400
#define FDIM 1920
#define HDIM 256
#define OUTC 260
#define NSLAB 4
#define KSLAB (FDIM/NSLAB)      // 480
#define NKT1 (KSLAB/16)         // 30
#define NKT2 (HDIM/16)          // 16
#define SCOREBLKS 200           // score blocks per batch
#define TRTILES 1536            // transpose tiles per batch

typedef unsigned long long ull;

// ---------------- scratch (static device globals; no allocation) ----------------
__device__ __align__(16) float g_conf[BATCH*NANCH];
__device__ int   g_cls [BATCH*NANCH];
__device__ int   g_hist[BATCH*NBINS];
__device__ __align__(16) float g_boxes[TOTDET*4];
__device__ float g_keep [TOTDET];
__device__ __align__(16) float g_t1[BATCH*6400*128];
__device__ __align__(16) float g_t2[BATCH*1600*256];
__device__ __align__(16) float g_t3[BATCH*400*512];
__device__ __align__(16) float g_t4[BATCH*100*1024];
__device__ __align__(16) float g_F [TOTDET*FDIM];
__device__ __align__(16) float g_part[NSLAB*TOTDET*HDIM];

// ---------------- asm helpers ----------------
__device__ __forceinline__ void cp16(void* s, const void* g) {
    unsigned ss = (unsigned)__cvta_generic_to_shared(s);
    asm volatile("cp.async.cg.shared.global [%0], [%1], 16;" :: "r"(ss), "l"(g));
}
#define CPCOMMIT asm volatile("cp.async.commit_group;" ::: "memory")
#define FFMA2(d,a,b) asm volatile("fma.rn.f32x2 %0, %1, %2, %0;" : "+l"(d) : "l"(a), "l"(b))
#define PACKDUP(d,x) asm volatile("mov.b64 %0, {%1, %1};" : "=l"(d) : "f"(x))
#define UNPACK2(lo,hi,v) asm volatile("mov.b64 {%0, %1}, %2;" : "=f"(lo), "=f"(hi) : "l"(v))

// ---------------- K1: fused score + transpose ----------------
__global__ void __launch_bounds__(256) prep_kernel(const float* __restrict__ preds,
        const float* __restrict__ f1, const float* __restrict__ f2,
        const float* __restrict__ f3, const float* __restrict__ f4) {
    __shared__ __align__(16) char smraw[128*PREDC*4 + NBINS*4];  // 47616B, reused by both paths
    int blk = blockIdx.x, b = blockIdx.y;
    int t = threadIdx.x;

    if (blk < SCOREBLKS) {
        // ---- score path: 128 anchors, 256 threads ----
        float* s = (float*)smraw;
        int* shist = (int*)(smraw + 128*PREDC*4);
        int n0 = blk * 128;
        int cnt = NANCH - n0; if (cnt > 128) cnt = 128;
        for (int i = t; i < NBINS; i += 256) shist[i] = 0;
        const float4* src = (const float4*)(preds + ((size_t)b*NANCH + n0) * PREDC);
        float4* s4 = (float4*)s;
        int tot4 = cnt * PREDC / 4;
        for (int i = t; i < tot4; i += 256) s4[i] = src[i];
        __syncthreads();
        if (t < cnt) {
            const float* a = s + t*PREDC;
            float obj = a[4];
            float best = a[5]*obj; int bc = 0;
            #pragma unroll 8
            for (int c = 1; c < NCLS; c++) {
                float v = a[5+c]*obj;
                if (v > best) { best = v; bc = c; }
            }
            float conf = best > 0.1f ? best : 0.f;
            g_conf[(size_t)b*NANCH + n0 + t] = conf;
            g_cls [(size_t)b*NANCH + n0 + t] = bc;
            if (conf > 0.1f) {
                int bin = (int)((conf - 0.1f) * (1024.f/0.9f));
                bin = min(max(bin, 0), NBINS-1);
                atomicAdd(&shist[bin], 1);
            }
        }
        __syncthreads();
        for (int i = t; i < NBINS; i += 256) {
            int v = shist[i];
            if (v) atomicAdd(&g_hist[b*NBINS + i], v);
        }
    } else {
        // ---- transpose path: 32x32 tile, float4 both sides ----
        float (*tile)[33] = (float(*)[33])smraw;
        int tl = blk - SCOREBLKS;
        const float* src; float* dst; int C, HW, tp;
        if (tl < 800)       {             src = f1; dst = g_t1; C = 128;  HW = 6400; tp = 200; }
        else if (tl < 1200) { tl -= 800;  src = f2; dst = g_t2; C = 256;  HW = 1600; tp = 50; }
        else if (tl < 1408) { tl -= 1200; src = f3; dst = g_t3; C = 512;  HW = 400;  tp = 13; }
        else                { tl -= 1408; src = f4; dst = g_t4; C = 1024; HW = 100;  tp = 4; }
        src += (size_t)b*C*HW; dst += (size_t)b*C*HW;
        int p0 = (tl % tp) * 32, c0 = (tl / tp) * 32;
        int tx = t & 7, ty = t >> 3;    // tx: 0..7 (x4 along fast dim), ty: 0..31
        // load: row c = c0+ty, float4 along p
        {
            int p = p0 + tx*4;
            if (p < HW) {
                float4 v = *(const float4*)(src + (size_t)(c0 + ty)*HW + p);
                tile[tx*4+0][ty] = v.x; tile[tx*4+1][ty] = v.y;
                tile[tx*4+2][ty] = v.z; tile[tx*4+3][ty] = v.w;
            }
        }
        __syncthreads();
        // store: row p = p0+ty, float4 along c
        {
            int p = p0 + ty;
            if (p < HW) {
                float4 v = make_float4(tile[ty][tx*4+0], tile[ty][tx*4+1],
                                       tile[ty][tx*4+2], tile[ty][tx*4+3]);
                *(float4*)(dst + (size_t)p*C + c0 + tx*4) = v;
            }
        }
    }
}

// ---------------- K2: fused threshold + compact + rank + NMS (self-zeroes g_hist) ----------------
__global__ void __launch_bounds__(1024) select_kernel(const float* __restrict__ preds) {
    __shared__ int s[NBINS];
    __shared__ int sthr, scnt;
    __shared__ float cc[CMAX];
    __shared__ int   ci[CMAX];
    __shared__ float tv[MAXDET];
    __shared__ int   tti[MAXDET];
    __shared__ float sx1[MAXDET], sy1[MAXDET], sx2[MAXDET], sy2[MAXDET], sar[MAXDET];
    __shared__ int   scls[MAXDET];
    __shared__ unsigned supm[MAXDET][10];
    __shared__ unsigned keepw[10];
    int b = blockIdx.x, t = threadIdx.x;

    // --- phase 1: suffix scan of histogram -> threshold bin (and re-zero for next replay) ---
    s[t] = g_hist[b*NBINS + t];
    g_hist[b*NBINS + t] = 0;
    __syncthreads();
    for (int off = 1; off < NBINS; off <<= 1) {
        int v = (t + off < NBINS) ? s[t + off] : 0;
        __syncthreads();
        s[t] += v;
        __syncthreads();
    }
    if (s[t] >= MAXDET && (t == NBINS-1 || s[t+1] < MAXDET)) sthr = t;
    if (t == 0) { if (s[0] < MAXDET) sthr = 0; scnt = 0; }
    __syncthreads();
    int thr = sthr;

    // --- phase 2: compact candidates into shared ---
    for (int i = t; i < NANCH; i += 1024) {
        float conf = g_conf[(size_t)b*NANCH + i];
        if (conf > 0.1f) {
            int bin = (int)((conf - 0.1f) * (1024.f/0.9f));
            bin = min(max(bin, 0), NBINS-1);
            if (bin >= thr) {
                int p = atomicAdd(&scnt, 1);
                if (p < CMAX) { cc[p] = conf; ci[p] = i; }
            }
        }
    }
    __syncthreads();
    int M = min(scnt, CMAX);

    // --- phase 3: exact stable rank -> top-300 ---
    if (t < MAXDET) { tv[t] = 0.f; tti[t] = 0; }
    __syncthreads();
    for (int i = t; i < M; i += 1024) {
        float c = cc[i]; int id = ci[i];
        int r = 0;
        for (int j = 0; j < M; j++) {
            float cj = cc[j];
            r += (cj > c) || (cj == c && ci[j] < id);
        }
        if (r < MAXDET) { tv[r] = c; tti[r] = id; }
    }
    __syncthreads();

    // --- phase 4: boxes + validity ---
    bool act = t < MAXDET;
    bool valid = false;
    if (act) {
        int idx = tti[t];
        float conf = tv[t];
        const float* p = preds + ((size_t)b*NANCH + idx) * PREDC;
        float xc = p[0], yc = p[1], w = p[2], h = p[3];
        float x1 = xc - w*0.5f, y1 = yc - h*0.5f;
        float x2 = xc + w*0.5f, y2 = yc + h*0.5f;
        float* gb = g_boxes + ((size_t)b*MAXDET + t)*4;
        gb[0]=x1; gb[1]=y1; gb[2]=x2; gb[3]=y2;
        int cls = g_cls[(size_t)b*NANCH + idx];
        float off = (float)cls * 4096.0f;
        float vx1 = x1+off, vy1 = y1+off, vx2 = x2+off, vy2 = y2+off;
        sx1[t]=vx1; sy1[t]=vy1; sx2[t]=vx2; sy2[t]=vy2;
        sar[t] = (vx2-vx1)*(vy2-vy1);
        scls[t] = cls;
        valid = conf > 0.1f;
    }
    if (t < 320) {
        unsigned vb = __ballot_sync(0xffffffffu, valid);
        if ((t & 31) == 0) keepw[t >> 5] = vb;
    }
    __syncthreads();

    // --- phase 5: suppression matrix, 32 warps over (i, word) jobs ---
    {
        int warp = t >> 5, lane = t & 31;
        for (int job = warp; job < MAXDET*10; job += 32) {
            int i = job / 10, word = job - i*10;
            int jb = word*32 + lane;
            int ic = scls[i];
            bool lact = (jb < MAXDET) && (jb > i);
            bool cm = lact && (scls[jb] == ic);
            unsigned anym = __ballot_sync(0xffffffffu, cm);
            bool sup = false;
            if (anym) {
                float ix1 = sx1[i], iy1 = sy1[i], ix2 = sx2[i], iy2 = sy2[i], iar = sar[i];
                if (cm) {
                    float lx = fmaxf(ix1, sx1[jb]), lyv = fmaxf(iy1, sy1[jb]);
                    float rx = fminf(ix2, sx2[jb]), ry  = fminf(iy2, sy2[jb]);
                    float iw = fmaxf(rx - lx, 0.f), ih = fmaxf(ry - lyv, 0.f);
                    float inter = iw * ih;
                    float iou = inter / (iar + sar[jb] - inter + 1e-7f);
                    sup = iou > 0.6f;
                }
            }
            unsigned m = __ballot_sync(0xffffffffu, sup);
            if (lane == 0) supm[i][word] = m;
        }
    }
    __syncthreads();

    // --- phase 6: greedy sweep (register keep words, ffs skip) ---
    if (t == 0) {
        unsigned kw[10];
        #pragma unroll
        for (int w = 0; w < 10; w++) kw[w] = keepw[w];
        #pragma unroll
        for (int w = 0; w < 10; w++) {
            unsigned bits = kw[w];
            while (bits) {
                int bit = __ffs(bits) - 1;
                bits &= bits - 1;
                int i = w*32 + bit;
                #pragma unroll
                for (int w2 = 0; w2 < 10; w2++) kw[w2] &= ~supm[i][w2];
                bits &= kw[w];
            }
        }
        #pragma unroll
        for (int w = 0; w < 10; w++) keepw[w] = kw[w];
    }
    __syncthreads();
    if (act) g_keep[b*MAXDET + t] = ((keepw[t>>5] >> (t&31)) & 1u) ? 1.f : 0.f;
}

// ---------------- K3: ROI align 1x1 (480 threads = one float4 chunk each) ----------------
__global__ void __launch_bounds__(480) roi_kernel() {
    int det = blockIdx.x, b = blockIdx.y;
    int row = b*MAXDET + det;
    const float* gb = g_boxes + (size_t)row*4;
    float bx1 = gb[0], by1 = gb[1], bx2 = gb[2], by2 = gb[3];
    int q = threadIdx.x;
    const float* T; int C, H, W; float scale; int c0;
    if (q < 32)       { T = g_t1 + (size_t)b*6400*128; C = 128;  H = 80; W = 80; scale = 0.125f;    c0 = q*4; }
    else if (q < 96)  { T = g_t2 + (size_t)b*1600*256; C = 256;  H = 40; W = 40; scale = 0.0625f;   c0 = (q-32)*4; }
    else if (q < 224) { T = g_t3 + (size_t)b*400*512;  C = 512;  H = 20; W = 20; scale = 0.03125f;  c0 = (q-96)*4; }
    else              { T = g_t4 + (size_t)b*100*1024; C = 1024; H = 10; W = 10; scale = 0.015625f; c0 = (q-224)*4; }

    float x1 = bx1*scale, y1 = by1*scale, x2 = bx2*scale, y2 = by2*scale;
    float w = fmaxf(x2-x1, 1.f), h = fmaxf(y2-y1, 1.f);
    float xs[2] = { x1 + 0.5f*(w*0.5f), x1 + 1.5f*(w*0.5f) };
    float ys[2] = { y1 + 0.5f*(h*0.5f), y1 + 1.5f*(h*0.5f) };
    int pos[16]; float wt[16];
    int k = 0;
    #pragma unroll
    for (int py = 0; py < 2; py++) {
        #pragma unroll
        for (int px = 0; px < 2; px++) {
            float y = fminf(fmaxf(ys[py], 0.f), (float)(H-1));
            float x = fminf(fmaxf(xs[px], 0.f), (float)(W-1));
            float y0f = floorf(y), x0f = floorf(x);
            int y0 = (int)y0f, x0 = (int)x0f;
            int y1i = min(y0+1, H-1), x1i = min(x0+1, W-1);
            float ly = y - y0f, lx = x - x0f;
            pos[k] = (y0 *W + x0 )*C; wt[k] = (1.f-ly)*(1.f-lx)*0.25f; k++;
            pos[k] = (y0 *W + x1i)*C; wt[k] = (1.f-ly)*lx*0.25f;       k++;
            pos[k] = (y1i*W + x0 )*C; wt[k] = ly*(1.f-lx)*0.25f;       k++;
            pos[k] = (y1i*W + x1i)*C; wt[k] = ly*lx*0.25f;             k++;
        }
    }
    float4 acc = make_float4(0.f, 0.f, 0.f, 0.f);
    #pragma unroll
    for (int i = 0; i < 16; i++) {
        float4 v = *(const float4*)(T + pos[i] + c0);
        float wv = wt[i];
        acc.x += wv*v.x; acc.y += wv*v.y; acc.z += wv*v.z; acc.w += wv*v.w;
    }
    *(float4*)(g_F + (size_t)row*FDIM + q*4) = acc;
}

// ---------------- K4: GEMM1 split-K (600 blocks, 64 thr, FFMA2, cp.async x2) ----------------
__global__ void __launch_bounds__(64) gemm1_kernel(const float* __restrict__ W1) {
    __shared__ __align__(16) float As[2][16][16];   // [stage][k][m]
    __shared__ __align__(16) float Bs[2][16][256];  // [stage][k][n]
    int m0 = blockIdx.x * 16;
    int slab = blockIdx.y;
    int kb = slab * KSLAB;
    int tid = threadIdx.x;
    int ar = tid >> 2, af = tid & 3;
    const float* Aptr = g_F + (size_t)(m0 + ar)*FDIM + kb + af*4;

    // prologue: stage 0
    {
        const float* bsrc = W1 + (size_t)kb*256 + tid*4;
        #pragma unroll
        for (int i = 0; i < 16; i++) cp16(&Bs[0][i][tid*4], bsrc + (size_t)i*256);
        CPCOMMIT;
        float4 av = *(const float4*)(Aptr);
        As[0][af*4+0][ar] = av.x; As[0][af*4+1][ar] = av.y;
        As[0][af*4+2][ar] = av.z; As[0][af*4+3][ar] = av.w;
    }

    int rg = tid >> 5;   // 0..1 -> rows rg*8..rg*8+7
    int cg = tid & 31;   // cols cg*4..+3 and 128+cg*4..+3
    ull acc[4][8];
    #pragma unroll
    for (int p = 0; p < 4; p++)
        #pragma unroll
        for (int j = 0; j < 8; j++) acc[p][j] = 0ull;

    #pragma unroll 1
    for (int kt = 0; kt < NKT1; kt++) {
        int st = kt & 1;
        if (kt + 1 < NKT1) {
            const float* bsrc = W1 + (size_t)(kb + (kt+1)*16)*256 + tid*4;
            #pragma unroll
            for (int i = 0; i < 16; i++) cp16(&Bs[st^1][i][tid*4], bsrc + (size_t)i*256);
            CPCOMMIT;
            float4 av = *(const float4*)(Aptr + (kt+1)*16);
            As[st^1][af*4+0][ar] = av.x; As[st^1][af*4+1][ar] = av.y;
            As[st^1][af*4+2][ar] = av.z; As[st^1][af*4+3][ar] = av.w;
            asm volatile("cp.async.wait_group 1;" ::: "memory");
        } else {
            asm volatile("cp.async.wait_group 0;" ::: "memory");
        }
        __syncthreads();
        #pragma unroll
        for (int k = 0; k < 16; k++) {
            ull a[4];
            #pragma unroll
            for (int p = 0; p < 4; p++)
                a[p] = *(const ull*)&As[st][k][rg*8 + 2*p];
            float4 b0 = *(const float4*)&Bs[st][k][cg*4];
            float4 b1 = *(const float4*)&Bs[st][k][128 + cg*4];
            ull bd[8];
            PACKDUP(bd[0], b0.x); PACKDUP(bd[1], b0.y); PACKDUP(bd[2], b0.z); PACKDUP(bd[3], b0.w);
            PACKDUP(bd[4], b1.x); PACKDUP(bd[5], b1.y); PACKDUP(bd[6], b1.z); PACKDUP(bd[7], b1.w);
            #pragma unroll
            for (int p = 0; p < 4; p++)
                #pragma unroll
                for (int j = 0; j < 8; j++) FFMA2(acc[p][j], a[p], bd[j]);
        }
        __syncthreads();
    }

    float* dst = g_part + ((size_t)slab*TOTDET + m0)*HDIM;
    #pragma unroll
    for (int p = 0; p < 4; p++) {
        float lo[8], hi[8];
        #pragma unroll
        for (int j = 0; j < 8; j++) UNPACK2(lo[j], hi[j], acc[p][j]);
        int r0 = rg*8 + 2*p;
        *(float4*)(dst + (size_t)r0*HDIM + cg*4)           = make_float4(lo[0],lo[1],lo[2],lo[3]);
        *(float4*)(dst + (size_t)r0*HDIM + 128 + cg*4)     = make_float4(lo[4],lo[5],lo[6],lo[7]);
        *(float4*)(dst + (size_t)(r0+1)*HDIM + cg*4)       = make_float4(hi[0],hi[1],hi[2],hi[3]);
        *(float4*)(dst + (size_t)(r0+1)*HDIM + 128 + cg*4) = make_float4(hi[4],hi[5],hi[6],hi[7]);
    }
}

// ---------------- K5: GEMM2 + slab reduce + bias/leaky + keep + bb ----------------
__global__ void __launch_bounds__(256) gemm2_kernel(const float* __restrict__ W2,
        const float* __restrict__ b1, const float* __restrict__ b2,
        const float* __restrict__ orig_hw, float* __restrict__ out) {
    __shared__ __align__(16) float Ah[HDIM][16];     // [k][m], 16KB
    __shared__ __align__(16) float Bs[2][16][256];   // 32KB
    int m0 = blockIdx.x * 16;
    int tid = threadIdx.x;

    // A panel: reduce 4 slabs + b1 + leaky, store transposed
    #pragma unroll
    for (int q = 0; q < 4; q++) {
        int pos = q*256 + tid;
        int r = pos >> 6, f = pos & 63;
        const float* p0 = g_part + ((size_t)(m0 + r))*HDIM + f*4;
        float4 s0 = *(const float4*)p0;
        float4 s1 = *(const float4*)(p0 + (size_t)TOTDET*HDIM);
        float4 s2 = *(const float4*)(p0 + (size_t)2*TOTDET*HDIM);
        float4 s3 = *(const float4*)(p0 + (size_t)3*TOTDET*HDIM);
        float4 bv = *(const float4*)(b1 + f*4);
        float v0 = s0.x+s1.x+s2.x+s3.x+bv.x; v0 = v0 > 0.f ? v0 : 0.01f*v0;
        float v1 = s0.y+s1.y+s2.y+s3.y+bv.y; v1 = v1 > 0.f ? v1 : 0.01f*v1;
        float v2 = s0.z+s1.z+s2.z+s3.z+bv.z; v2 = v2 > 0.f ? v2 : 0.01f*v2;
        float v3 = s0.w+s1.w+s2.w+s3.w+bv.w; v3 = v3 > 0.f ? v3 : 0.01f*v3;
        Ah[f*4+0][r] = v0; Ah[f*4+1][r] = v1; Ah[f*4+2][r] = v2; Ah[f*4+3][r] = v3;
    }

    // prologue B stage 0
    {
        int br = tid >> 6, bf = tid & 63;
        #pragma unroll
        for (int i = 0; i < 4; i++)
            cp16(&Bs[0][br + i*4][bf*4], W2 + (size_t)(br + i*4)*256 + bf*4);
        CPCOMMIT;
    }
    __syncthreads();

    int ty = tid >> 6, tx = tid & 63;
    ull acc[2][4];
    #pragma unroll
    for (int h = 0; h < 2; h++)
        #pragma unroll
        for (int j = 0; j < 4; j++) acc[h][j] = 0ull;

    #pragma unroll 1
    for (int kt = 0; kt < NKT2; kt++) {
        int st = kt & 1;
        if (kt + 1 < NKT2) {
            int br = tid >> 6, bf = tid & 63;
            #pragma unroll
            for (int i = 0; i < 4; i++)
                cp16(&Bs[st^1][br + i*4][bf*4], W2 + (size_t)((kt+1)*16 + br + i*4)*256 + bf*4);
            CPCOMMIT;
            asm volatile("cp.async.wait_group 1;" ::: "memory");
        } else {
            asm volatile("cp.async.wait_group 0;" ::: "memory");
        }
        __syncthreads();
        #pragma unroll
        for (int k = 0; k < 16; k++) {
            int kk = kt*16 + k;
            ull a0 = *(const ull*)&Ah[kk][ty*4];
            ull a1 = *(const ull*)&Ah[kk][ty*4 + 2];
            float4 bq = *(const float4*)&Bs[st][k][tx*4];
            ull bd[4];
            PACKDUP(bd[0], bq.x); PACKDUP(bd[1], bq.y); PACKDUP(bd[2], bq.z); PACKDUP(bd[3], bq.w);
            #pragma unroll
            for (int j = 0; j < 4; j++) { FFMA2(acc[0][j], a0, bd[j]); FFMA2(acc[1][j], a1, bd[j]); }
        }
        __syncthreads();
    }

    // epilogue: b2 + leaky + keep, write h part
    float4 bv2 = *(const float4*)(b2 + tx*4);
    float bb2[4] = { bv2.x, bv2.y, bv2.z, bv2.w };
    #pragma unroll
    for (int h = 0; h < 2; h++) {
        float lo[4], hi[4];
        #pragma unroll
        for (int j = 0; j < 4; j++) UNPACK2(lo[j], hi[j], acc[h][j]);
        int mr = m0 + ty*4 + 2*h;
        float kf0 = g_keep[mr], kf1 = g_keep[mr+1];
        float o0[4], o1[4];
        #pragma unroll
        for (int j = 0; j < 4; j++) {
            float v = lo[j] + bb2[j]; v = v > 0.f ? v : 0.01f*v; o0[j] = v * kf0;
            float u = hi[j] + bb2[j]; u = u > 0.f ? u : 0.01f*u; o1[j] = u * kf1;
        }
        *(float4*)(out + (size_t)mr*OUTC + 4 + tx*4)     = make_float4(o0[0],o0[1],o0[2],o0[3]);
        *(float4*)(out + (size_t)(mr+1)*OUTC + 4 + tx*4) = make_float4(o1[0],o1[1],o1[2],o1[3]);
    }

    // bb rescale (cols 0..3)
    if (tid < 16) {
        int m = m0 + tid;
        int bidx = m / MAXDET;
        const float* gb = g_boxes + (size_t)m*4;
        float oh = orig_hw[bidx*2 + 0], ow = orig_hw[bidx*2 + 1];
        float gain = fminf(640.f/oh, 640.f/ow);
        float padx = (640.f - ow*gain) * 0.5f;
        float pady = (640.f - oh*gain) * 0.5f;
        float kf = g_keep[m];
        float x1 = fminf(fmaxf((gb[0]-padx)/gain, 0.f), ow);
        float y1 = fminf(fmaxf((gb[1]-pady)/gain, 0.f), oh);
        float x2 = fminf(fmaxf((gb[2]-padx)/gain, 0.f), ow);
        float y2 = fminf(fmaxf((gb[3]-pady)/gain, 0.f), oh);
        *(float4*)(out + (size_t)m*OUTC) = make_float4(x1/ow*kf, y1/oh*kf, x2/ow*kf, y2/oh*kf);
    }
}

// ---------------- launch ----------------
extern "C" void kernel_launch(void* const* d_in, const int* in_sizes, int n_in,
                              void* d_out, int out_size) {
    const float* preds   = (const float*)d_in[0];
    const float* feat1   = (const float*)d_in[1];
    const float* feat2   = (const float*)d_in[2];
    const float* feat3   = (const float*)d_in[3];
    const float* feat4   = (const float*)d_in[4];
    const float* orig_hw = (const float*)d_in[5];
    const float* W1      = (const float*)d_in[6];
    const float* b1      = (const float*)d_in[7];
    const float* W2      = (const float*)d_in[8];
    const float* b2      = (const float*)d_in[9];
    float* out = (float*)d_out;
    (void)in_sizes; (void)n_in; (void)out_size;

    prep_kernel<<<dim3(SCOREBLKS + TRTILES, BATCH), 256>>>(preds, feat1, feat2, feat3, feat4);
    select_kernel<<<BATCH, 1024>>>(preds);
    roi_kernel<<<dim3(MAXDET, BATCH), 480>>>();
    gemm1_kernel<<<dim3(TOTDET/16, NSLAB), 64>>>(W1);
    gemm2_kernel<<<TOTDET/16, 256>>>(W2, b1, b2, orig_hw, out);
}